// round 5
// baseline (speedup 1.0000x reference)
#include <cuda_runtime.h>
#include <math.h>

#define BB 32
#define SS 256
#define TT 256
#define HH 4096
#define EE 64
#define EPS_V 1e-6f
#define CHUNK 256

// ---------------- scratch (no allocations allowed) ----------------
__device__ float g_m[BB * HH];        // sum over s of input_embeds  (512 KB)
__device__ float g_cond[BB * EE];     // cond[:, :E]                 (8 KB)
__device__ float g_pbpd[TT * HH];     // prompt_base + prompt_delta  (4 MB)
__device__ float4 g_w[BB * TT];       // top-4 weights, pre-scaled by (1-g)
__device__ int4 g_idx[BB * TT];       // top-4 expert indices
__device__ unsigned int g_Hbits;      // max|H_slice| as uint bits
__device__ unsigned int g_Dbits;      // max|d_slice| as uint bits

// ---------------- K0: reset atomic-max scalars ----------------
__global__ void k_reset() {
    g_Hbits = 0u;
    g_Dbits = 0u;
}

// ---------------- K1: m[b,h] = sum_s x[b,s,h] ----------------
__global__ __launch_bounds__(256) void k_reduce_s(const float* __restrict__ x) {
    int b = blockIdx.y;
    int h = blockIdx.x * 256 + threadIdx.x;
    const float* p = x + (size_t)b * SS * HH + h;
    float acc = 0.f;
#pragma unroll 16
    for (int s = 0; s < SS; ++s) acc += p[(size_t)s * HH];
    g_m[b * HH + h] = acc;
}

// ---------------- K2: pbpd = pb + pd (float4) ----------------
__global__ __launch_bounds__(256) void k_pbpd(const float* __restrict__ pb,
                                              const float* __restrict__ pd) {
    int i = blockIdx.x * 256 + threadIdx.x;
    float4 a = ((const float4*)pb)[i];
    float4 c = ((const float4*)pd)[i];
    ((float4*)g_pbpd)[i] = make_float4(a.x + c.x, a.y + c.y, a.z + c.z, a.w + c.w);
}

// ---------------- K3: cond[b,e] = (1/S) * sum_h m[b,h]*W[e,h], e < E ----------------
// grid (EE, BB/8), block 256. W row staged in smem, 8 batch rows per block.
__global__ __launch_bounds__(256) void k_cond(const float* __restrict__ W) {
    __shared__ float4 sw[HH / 4];
    __shared__ float sred[8 * 8];
    int e = blockIdx.x;
    int bg = blockIdx.y * 8;
    int tid = threadIdx.x;

    const float4* wrow = (const float4*)(W + (size_t)e * HH);
#pragma unroll
    for (int i = tid; i < HH / 4; i += 256) sw[i] = wrow[i];
    __syncthreads();

    float acc[8];
#pragma unroll
    for (int j = 0; j < 8; ++j) acc[j] = 0.f;

#pragma unroll
    for (int i = tid; i < HH / 4; i += 256) {
        float4 w = sw[i];
#pragma unroll
        for (int j = 0; j < 8; ++j) {
            float4 m = ((const float4*)(g_m + (size_t)(bg + j) * HH))[i];
            acc[j] += w.x * m.x + w.y * m.y + w.z * m.z + w.w * m.w;
        }
    }
    int warp = tid >> 5, lane = tid & 31;
#pragma unroll
    for (int j = 0; j < 8; ++j) {
        float v = acc[j];
#pragma unroll
        for (int o = 16; o > 0; o >>= 1) v += __shfl_down_sync(0xffffffffu, v, o);
        if (lane == 0) sred[j * 8 + warp] = v;
    }
    __syncthreads();
    if (tid < 8) {
        float v = 0.f;
#pragma unroll
        for (int w2 = 0; w2 < 8; ++w2) v += sred[tid * 8 + w2];
        g_cond[(bg + tid) * EE + e] = v * (1.0f / SS);
    }
}

// ---------------- K4: global scales via atomicMax on float bits ----------------
__global__ __launch_bounds__(256) void k_scales(const float* __restrict__ pb,
                                                const float* __restrict__ pd) {
    float hmax = 0.f, dmax = 0.f;
    int stride = gridDim.x * blockDim.x;
    int base = blockIdx.x * blockDim.x + threadIdx.x;
    for (int i = base; i < BB * TT * EE; i += stride) {
        int e = i & (EE - 1);
        int t = (i >> 6) & (TT - 1);
        int b = i >> 14;
        hmax = fmaxf(hmax, fabsf(pb[t * HH + e] + g_cond[b * EE + e]));
    }
    for (int i = base; i < TT * EE; i += stride) {
        int e = i & (EE - 1);
        int t = i >> 6;
        dmax = fmaxf(dmax, fabsf(pd[t * HH + e]));
    }
#pragma unroll
    for (int o = 16; o > 0; o >>= 1) {
        hmax = fmaxf(hmax, __shfl_down_sync(0xffffffffu, hmax, o));
        dmax = fmaxf(dmax, __shfl_down_sync(0xffffffffu, dmax, o));
    }
    __shared__ float shm[8], sdm[8];
    if ((threadIdx.x & 31) == 0) {
        shm[threadIdx.x >> 5] = hmax;
        sdm[threadIdx.x >> 5] = dmax;
    }
    __syncthreads();
    if (threadIdx.x == 0) {
        float hv = shm[0], dv = sdm[0];
#pragma unroll
        for (int j = 1; j < 8; ++j) {
            hv = fmaxf(hv, shm[j]);
            dv = fmaxf(dv, sdm[j]);
        }
        atomicMax(&g_Hbits, __float_as_uint(hv));
        atomicMax(&g_Dbits, __float_as_uint(dv));
    }
}

// ---------------- K5: per-(b,t) top-4 indices + pre-scaled weights ----------------
// grid (TT, BB), block 64.
__global__ __launch_bounds__(64) void k_weights(const float* __restrict__ pb,
                                                const float* __restrict__ pd,
                                                const float* __restrict__ gamma) {
    int t = blockIdx.x, b = blockIdx.y;
    int tid = threadIdx.x;
    __shared__ float s_log[EE];

    float invHs = 1.f / fmaxf(__uint_as_float(g_Hbits), EPS_V);
    float invDs = 1.f / fmaxf(__uint_as_float(g_Dbits), EPS_V);

    s_log[tid] = 0.5f * (pb[t * HH + tid] + g_cond[b * EE + tid]) * invHs +
                 0.5f * pd[t * HH + tid] * invDs;
    __syncthreads();

    if (tid == 0) {
        float bv0 = -3.4e38f, bv1 = -3.4e38f, bv2 = -3.4e38f, bv3 = -3.4e38f;
        int bi0 = 0, bi1 = 0, bi2 = 0, bi3 = 0;
#pragma unroll
        for (int e = 0; e < EE; ++e) {
            float v = s_log[e];
            if (v > bv0) {
                bv3 = bv2; bi3 = bi2; bv2 = bv1; bi2 = bi1;
                bv1 = bv0; bi1 = bi0; bv0 = v; bi0 = e;
            } else if (v > bv1) {
                bv3 = bv2; bi3 = bi2; bv2 = bv1; bi2 = bi1; bv1 = v; bi1 = e;
            } else if (v > bv2) {
                bv3 = bv2; bi3 = bi2; bv2 = v; bi2 = e;
            } else if (v > bv3) {
                bv3 = v; bi3 = e;
            }
        }
        float e1 = __expf(bv1 - bv0);
        float e2 = __expf(bv2 - bv0);
        float e3 = __expf(bv3 - bv0);
        float g = 1.f / (1.f + __expf(-gamma[0]));
        float scale = (1.f - g) / (1.0f + e1 + e2 + e3);
        g_w[b * TT + t] = make_float4(scale, e1 * scale, e2 * scale, e3 * scale);
        g_idx[b * TT + t] = make_int4(bi0, bi1, bi2, bi3);
    }
}

// ---------------- K6: output with smem-staged experts ----------------
// grid (HH/CHUNK, BB), block 256. Dynamic smem:
//   [0, 64*CHUNK)            : all 64 expert rows for this h-chunk
//   then float4 s_w[TT], int4 s_i[TT] : this batch's weight table
__global__ __launch_bounds__(256) void k_out2(const float* __restrict__ limes,
                                              const float* __restrict__ shv,
                                              const float* __restrict__ gamma,
                                              float* __restrict__ out) {
    extern __shared__ float sm[];
    float* s_lime = sm;                               // 64*256 floats = 64 KB
    float4* s_w = (float4*)(sm + EE * CHUNK);         // 256 * 16B = 4 KB
    int4* s_i = (int4*)(s_w + TT);                    // 256 * 16B = 4 KB

    int chunk = blockIdx.x, b = blockIdx.y;
    int tid = threadIdx.x;
    int base = chunk * CHUNK;

#pragma unroll
    for (int e = 0; e < EE; ++e)
        s_lime[e * CHUNK + tid] = limes[(size_t)e * HH + base + tid];
    s_w[tid] = g_w[b * TT + tid];
    s_i[tid] = g_idx[b * TT + tid];

    float g = 1.f / (1.f + __expf(-gamma[0]));
    float gsh = g * shv[base + tid];
    __syncthreads();

    const float* P = g_pbpd + base + tid;
    float* O = out + (size_t)b * TT * HH + base + tid;

#pragma unroll 4
    for (int t = 0; t < TT; ++t) {
        float4 w = s_w[t];
        int4 ix = s_i[t];
        float p = P[(size_t)t * HH];
        float mix = gsh + w.x * s_lime[ix.x * CHUNK + tid]
                        + w.y * s_lime[ix.y * CHUNK + tid]
                        + w.z * s_lime[ix.z * CHUNK + tid]
                        + w.w * s_lime[ix.w * CHUNK + tid];
        O[(size_t)t * HH] = p * mix;
    }
}

extern "C" void kernel_launch(void* const* d_in, const int* in_sizes, int n_in,
                              void* d_out, int out_size) {
    const float* x     = (const float*)d_in[0];  // input_embeds (B,S,H)
    const float* pb    = (const float*)d_in[1];  // prompt_base  (T,H)
    const float* pd    = (const float*)d_in[2];  // prompt_delta (T,H)
    const float* limes = (const float*)d_in[3];  // LiMEs        (E,H)
    const float* shv   = (const float*)d_in[4];  // LiME_shared  (H,)
    const float* gamma = (const float*)d_in[5];  // gamma        (1,)
    const float* W     = (const float*)d_in[6];  // W_proj       (H,H)
    float* out = (float*)d_out;                  // (B,T,H) f32

    static bool attr_set = false;
    if (!attr_set) {
        cudaFuncSetAttribute(k_out2, cudaFuncAttributeMaxDynamicSharedMemorySize,
                             EE * CHUNK * 4 + TT * 32);
        attr_set = true;
    }

    k_reset<<<1, 1>>>();
    k_reduce_s<<<dim3(HH / 256, BB), 256>>>(x);
    k_pbpd<<<TT * HH / 1024, 256>>>(pb, pd);
    k_cond<<<dim3(EE, BB / 8), 256>>>(W);
    k_scales<<<256, 256>>>(pb, pd);
    k_weights<<<dim3(TT, BB), 64>>>(pb, pd, gamma);
    k_out2<<<dim3(HH / CHUNK, BB), 256, EE * CHUNK * 4 + TT * 32>>>(limes, shv, gamma, out);
}

// round 7
// speedup vs baseline: 1.6348x; 1.6348x over previous
#include <cuda_runtime.h>
#include <math.h>

#define BB 32
#define SS 256
#define TT 256
#define HH 4096
#define EE 64
#define EPS_V 1e-6f
#define CHUNK 128

// ---------------- scratch (no allocations allowed) ----------------
__device__ float g_m[BB * HH];        // sum over s of input_embeds  (512 KB)
__device__ float g_cond[BB * EE];     // cond[:, :E]                 (8 KB)
__device__ float g_pbpd[TT * HH];     // prompt_base + prompt_delta  (4 MB)
__device__ float4 g_w[BB * TT];       // top-4 weights, pre-scaled by (1-g)
__device__ int4 g_idx[BB * TT];       // top-4 expert indices
__device__ unsigned int g_Hbits;      // max|H_slice| as uint bits
__device__ unsigned int g_Dbits;      // max|d_slice| as uint bits

// ---------------- K0: reset atomic-max scalars ----------------
__global__ void k_reset() {
    g_Hbits = 0u;
    g_Dbits = 0u;
}

// ---------------- K1: m[b,h] = sum_s x[b,s,h] ----------------
__global__ __launch_bounds__(256) void k_reduce_s(const float* __restrict__ x) {
    int b = blockIdx.y;
    int h = blockIdx.x * 256 + threadIdx.x;
    const float* p = x + (size_t)b * SS * HH + h;
    float acc = 0.f;
#pragma unroll 16
    for (int s = 0; s < SS; ++s) acc += p[(size_t)s * HH];
    g_m[b * HH + h] = acc;
}

// ---------------- K2: pbpd = pb + pd (float4) ----------------
__global__ __launch_bounds__(256) void k_pbpd(const float* __restrict__ pb,
                                              const float* __restrict__ pd) {
    int i = blockIdx.x * 256 + threadIdx.x;
    float4 a = ((const float4*)pb)[i];
    float4 c = ((const float4*)pd)[i];
    ((float4*)g_pbpd)[i] = make_float4(a.x + c.x, a.y + c.y, a.z + c.z, a.w + c.w);
}

// ---------------- K3: cond[b,e] = (1/S) * sum_h m[b,h]*W[e,h], e < E ----------------
// grid (EE, BB/8), block 256. W row staged in smem, 8 batch rows per block.
__global__ __launch_bounds__(256) void k_cond(const float* __restrict__ W) {
    __shared__ float4 sw[HH / 4];
    __shared__ float sred[8 * 8];
    int e = blockIdx.x;
    int bg = blockIdx.y * 8;
    int tid = threadIdx.x;

    const float4* wrow = (const float4*)(W + (size_t)e * HH);
#pragma unroll
    for (int i = tid; i < HH / 4; i += 256) sw[i] = wrow[i];
    __syncthreads();

    float acc[8];
#pragma unroll
    for (int j = 0; j < 8; ++j) acc[j] = 0.f;

#pragma unroll
    for (int i = tid; i < HH / 4; i += 256) {
        float4 w = sw[i];
#pragma unroll
        for (int j = 0; j < 8; ++j) {
            float4 m = ((const float4*)(g_m + (size_t)(bg + j) * HH))[i];
            acc[j] += w.x * m.x + w.y * m.y + w.z * m.z + w.w * m.w;
        }
    }
    int warp = tid >> 5, lane = tid & 31;
#pragma unroll
    for (int j = 0; j < 8; ++j) {
        float v = acc[j];
#pragma unroll
        for (int o = 16; o > 0; o >>= 1) v += __shfl_down_sync(0xffffffffu, v, o);
        if (lane == 0) sred[j * 8 + warp] = v;
    }
    __syncthreads();
    if (tid < 8) {
        float v = 0.f;
#pragma unroll
        for (int w2 = 0; w2 < 8; ++w2) v += sred[tid * 8 + w2];
        g_cond[(bg + tid) * EE + e] = v * (1.0f / SS);
    }
}

// ---------------- K4: global scales via atomicMax on float bits ----------------
__global__ __launch_bounds__(256) void k_scales(const float* __restrict__ pb,
                                                const float* __restrict__ pd) {
    float hmax = 0.f, dmax = 0.f;
    int stride = gridDim.x * blockDim.x;
    int base = blockIdx.x * blockDim.x + threadIdx.x;
    for (int i = base; i < BB * TT * EE; i += stride) {
        int e = i & (EE - 1);
        int t = (i >> 6) & (TT - 1);
        int b = i >> 14;
        hmax = fmaxf(hmax, fabsf(pb[t * HH + e] + g_cond[b * EE + e]));
    }
    for (int i = base; i < TT * EE; i += stride) {
        int e = i & (EE - 1);
        int t = i >> 6;
        dmax = fmaxf(dmax, fabsf(pd[t * HH + e]));
    }
#pragma unroll
    for (int o = 16; o > 0; o >>= 1) {
        hmax = fmaxf(hmax, __shfl_down_sync(0xffffffffu, hmax, o));
        dmax = fmaxf(dmax, __shfl_down_sync(0xffffffffu, dmax, o));
    }
    __shared__ float shm[8], sdm[8];
    if ((threadIdx.x & 31) == 0) {
        shm[threadIdx.x >> 5] = hmax;
        sdm[threadIdx.x >> 5] = dmax;
    }
    __syncthreads();
    if (threadIdx.x == 0) {
        float hv = shm[0], dv = sdm[0];
#pragma unroll
        for (int j = 1; j < 8; ++j) {
            hv = fmaxf(hv, shm[j]);
            dv = fmaxf(dv, sdm[j]);
        }
        atomicMax(&g_Hbits, __float_as_uint(hv));
        atomicMax(&g_Dbits, __float_as_uint(dv));
    }
}

// ---------------- K5: per-(b,t) top-4 indices + pre-scaled weights ----------------
// grid (TT, BB), block 64.
__global__ __launch_bounds__(64) void k_weights(const float* __restrict__ pb,
                                                const float* __restrict__ pd,
                                                const float* __restrict__ gamma) {
    int t = blockIdx.x, b = blockIdx.y;
    int tid = threadIdx.x;
    __shared__ float s_log[EE];

    float invHs = 1.f / fmaxf(__uint_as_float(g_Hbits), EPS_V);
    float invDs = 1.f / fmaxf(__uint_as_float(g_Dbits), EPS_V);

    s_log[tid] = 0.5f * (pb[t * HH + tid] + g_cond[b * EE + tid]) * invHs +
                 0.5f * pd[t * HH + tid] * invDs;
    __syncthreads();

    if (tid == 0) {
        float bv0 = -3.4e38f, bv1 = -3.4e38f, bv2 = -3.4e38f, bv3 = -3.4e38f;
        int bi0 = 0, bi1 = 0, bi2 = 0, bi3 = 0;
#pragma unroll
        for (int e = 0; e < EE; ++e) {
            float v = s_log[e];
            if (v > bv0) {
                bv3 = bv2; bi3 = bi2; bv2 = bv1; bi2 = bi1;
                bv1 = bv0; bi1 = bi0; bv0 = v; bi0 = e;
            } else if (v > bv1) {
                bv3 = bv2; bi3 = bi2; bv2 = bv1; bi2 = bi1; bv1 = v; bi1 = e;
            } else if (v > bv2) {
                bv3 = bv2; bi3 = bi2; bv2 = v; bi2 = e;
            } else if (v > bv3) {
                bv3 = v; bi3 = e;
            }
        }
        float e1 = __expf(bv1 - bv0);
        float e2 = __expf(bv2 - bv0);
        float e3 = __expf(bv3 - bv0);
        float g = 1.f / (1.f + __expf(-gamma[0]));
        float scale = (1.f - g) / (1.0f + e1 + e2 + e3);
        g_w[b * TT + t] = make_float4(scale, e1 * scale, e2 * scale, e3 * scale);
        g_idx[b * TT + t] = make_int4(bi0, bi1, bi2, bi3);
    }
}

// ---------------- K6: output with smem-staged experts ----------------
// grid (HH/CHUNK, BB), block 128 (= CHUNK). Dynamic smem (40 KB, <48 KB default):
//   s_lime[EE*CHUNK]  : all 64 expert rows for this h-chunk   (32 KB)
//   s_w[TT], s_i[TT]  : this batch's weight table             (8 KB)
// Latency fixes vs R4: (a) 8 independent pbpd LDGs batched per unrolled group
// (MLP_p1=8), (b) __stcs streaming stores so the 134 MB out-stream doesn't
// evict g_pbpd from L2, (c) 40 KB smem -> 5 blocks/SM.
__global__ __launch_bounds__(128) void k_out2(const float* __restrict__ limes,
                                              const float* __restrict__ shv,
                                              const float* __restrict__ gamma,
                                              float* __restrict__ out) {
    extern __shared__ float sm[];
    float* s_lime = sm;                               // 64*128 floats = 32 KB
    float4* s_w = (float4*)(sm + EE * CHUNK);         // 256 * 16B = 4 KB
    int4* s_i = (int4*)(s_w + TT);                    // 256 * 16B = 4 KB

    int chunk = blockIdx.x, b = blockIdx.y;
    int tid = threadIdx.x;
    int base = chunk * CHUNK;

#pragma unroll
    for (int e = 0; e < EE; ++e)
        s_lime[e * CHUNK + tid] = limes[(size_t)e * HH + base + tid];
#pragma unroll
    for (int t = tid; t < TT; t += CHUNK) {
        s_w[t] = g_w[b * TT + t];
        s_i[t] = g_idx[b * TT + t];
    }

    float g = 1.f / (1.f + __expf(-gamma[0]));
    float gsh = g * shv[base + tid];
    __syncthreads();

    const float* P = g_pbpd + base + tid;
    float* O = out + (size_t)b * TT * HH + base + tid;

    for (int t0 = 0; t0 < TT; t0 += 8) {
        float p[8];
#pragma unroll
        for (int j = 0; j < 8; ++j) p[j] = P[(size_t)(t0 + j) * HH];
#pragma unroll
        for (int j = 0; j < 8; ++j) {
            float4 w = s_w[t0 + j];
            int4 ix = s_i[t0 + j];
            float mix = gsh + w.x * s_lime[ix.x * CHUNK + tid]
                            + w.y * s_lime[ix.y * CHUNK + tid]
                            + w.z * s_lime[ix.z * CHUNK + tid]
                            + w.w * s_lime[ix.w * CHUNK + tid];
            __stcs(O + (size_t)(t0 + j) * HH, p[j] * mix);
        }
    }
}

extern "C" void kernel_launch(void* const* d_in, const int* in_sizes, int n_in,
                              void* d_out, int out_size) {
    const float* x     = (const float*)d_in[0];  // input_embeds (B,S,H)
    const float* pb    = (const float*)d_in[1];  // prompt_base  (T,H)
    const float* pd    = (const float*)d_in[2];  // prompt_delta (T,H)
    const float* limes = (const float*)d_in[3];  // LiMEs        (E,H)
    const float* shv   = (const float*)d_in[4];  // LiME_shared  (H,)
    const float* gamma = (const float*)d_in[5];  // gamma        (1,)
    const float* W     = (const float*)d_in[6];  // W_proj       (H,H)
    float* out = (float*)d_out;                  // (B,T,H) f32

    k_reset<<<1, 1>>>();
    k_reduce_s<<<dim3(HH / 256, BB), 256>>>(x);
    k_pbpd<<<TT * HH / 1024, 256>>>(pb, pd);
    k_cond<<<dim3(EE, BB / 8), 256>>>(W);
    k_scales<<<256, 256>>>(pb, pd);
    k_weights<<<dim3(TT, BB), 64>>>(pb, pd, gamma);
    k_out2<<<dim3(HH / CHUNK, BB), CHUNK, EE * CHUNK * 4 + TT * 32>>>(limes, shv, gamma, out);
}

// round 8
// speedup vs baseline: 2.0234x; 1.2377x over previous
#include <cuda_runtime.h>
#include <math.h>

#define BB 32
#define SS 256
#define TT 256
#define HH 4096
#define EE 64
#define EPS_V 1e-6f
#define CHUNK 256      // h per k_out2 block
#define TSPLIT 2
#define THALF (TT / TSPLIT)
#define SMEM_OUT2 (EE * CHUNK * 4 + THALF * 32)  // 64KB experts + 4KB weights

// ---------------- scratch (no allocations allowed) ----------------
__device__ float g_m[BB * HH];        // sum over s of input_embeds  (512 KB)
__device__ float g_cond[BB * EE];     // cond[:, :E]                 (8 KB)
__device__ float g_pbpd[TT * HH];     // prompt_base + prompt_delta  (4 MB)
__device__ float4 g_w[BB * TT];       // top-4 weights, pre-scaled by (1-g)
__device__ int4 g_idx[BB * TT];       // top-4 expert indices
__device__ unsigned int g_Hbits;      // max|H_slice| as uint bits
__device__ unsigned int g_Dbits;      // max|d_slice| as uint bits

// ---------------- K1: m[b,h] = sum_s x[b,s,h] ----------------
__global__ __launch_bounds__(256) void k_reduce_s(const float* __restrict__ x) {
    int b = blockIdx.y;
    int h = blockIdx.x * 256 + threadIdx.x;
    const float* p = x + (size_t)b * SS * HH + h;
    float acc = 0.f;
#pragma unroll 16
    for (int s = 0; s < SS; ++s) acc += p[(size_t)s * HH];
    g_m[b * HH + h] = acc;
}

// ---------------- K2: pbpd = pb + pd (float4); also resets max scalars ----------------
__global__ __launch_bounds__(256) void k_pbpd(const float* __restrict__ pb,
                                              const float* __restrict__ pd) {
    if (blockIdx.x == 0 && threadIdx.x == 0) {
        g_Hbits = 0u;
        g_Dbits = 0u;
    }
    int i = blockIdx.x * 256 + threadIdx.x;
    float4 a = ((const float4*)pb)[i];
    float4 c = ((const float4*)pd)[i];
    ((float4*)g_pbpd)[i] = make_float4(a.x + c.x, a.y + c.y, a.z + c.z, a.w + c.w);
}

// ---------------- K3: cond[b,e] = (1/S) * sum_h m[b,h]*W[e,h], e < E ----------------
// grid (EE, BB/2), block 256. 2 batch rows per block; W row via L2 (shared by 16 blocks).
__global__ __launch_bounds__(256) void k_cond(const float* __restrict__ W) {
    int e = blockIdx.x;
    int bg = blockIdx.y * 2;
    int tid = threadIdx.x;
    const float4* w = (const float4*)(W + (size_t)e * HH);
    const float4* m0 = (const float4*)(g_m + (size_t)bg * HH);
    const float4* m1 = (const float4*)(g_m + (size_t)(bg + 1) * HH);

    float a0 = 0.f, a1 = 0.f;
#pragma unroll
    for (int i = tid; i < HH / 4; i += 256) {
        float4 wv = __ldg(w + i);
        float4 v0 = m0[i];
        float4 v1 = m1[i];
        a0 += wv.x * v0.x + wv.y * v0.y + wv.z * v0.z + wv.w * v0.w;
        a1 += wv.x * v1.x + wv.y * v1.y + wv.z * v1.z + wv.w * v1.w;
    }
#pragma unroll
    for (int o = 16; o > 0; o >>= 1) {
        a0 += __shfl_down_sync(0xffffffffu, a0, o);
        a1 += __shfl_down_sync(0xffffffffu, a1, o);
    }
    __shared__ float sred[2][8];
    int warp = tid >> 5, lane = tid & 31;
    if (lane == 0) {
        sred[0][warp] = a0;
        sred[1][warp] = a1;
    }
    __syncthreads();
    if (tid < 2) {
        float v = 0.f;
#pragma unroll
        for (int j = 0; j < 8; ++j) v += sred[tid][j];
        g_cond[(bg + tid) * EE + e] = v * (1.0f / SS);
    }
}

// ---------------- K4: global scales via atomicMax on float bits ----------------
__global__ __launch_bounds__(256) void k_scales(const float* __restrict__ pb,
                                                const float* __restrict__ pd) {
    float hmax = 0.f, dmax = 0.f;
    int stride = gridDim.x * blockDim.x;
    int base = blockIdx.x * blockDim.x + threadIdx.x;
    for (int i = base; i < BB * TT * EE; i += stride) {
        int e = i & (EE - 1);
        int t = (i >> 6) & (TT - 1);
        int b = i >> 14;
        hmax = fmaxf(hmax, fabsf(pb[t * HH + e] + g_cond[b * EE + e]));
    }
    for (int i = base; i < TT * EE; i += stride) {
        int e = i & (EE - 1);
        int t = i >> 6;
        dmax = fmaxf(dmax, fabsf(pd[t * HH + e]));
    }
#pragma unroll
    for (int o = 16; o > 0; o >>= 1) {
        hmax = fmaxf(hmax, __shfl_down_sync(0xffffffffu, hmax, o));
        dmax = fmaxf(dmax, __shfl_down_sync(0xffffffffu, dmax, o));
    }
    __shared__ float shm[8], sdm[8];
    if ((threadIdx.x & 31) == 0) {
        shm[threadIdx.x >> 5] = hmax;
        sdm[threadIdx.x >> 5] = dmax;
    }
    __syncthreads();
    if (threadIdx.x == 0) {
        float hv = shm[0], dv = sdm[0];
#pragma unroll
        for (int j = 1; j < 8; ++j) {
            hv = fmaxf(hv, shm[j]);
            dv = fmaxf(dv, sdm[j]);
        }
        atomicMax(&g_Hbits, __float_as_uint(hv));
        atomicMax(&g_Dbits, __float_as_uint(dv));
    }
}

// ---------------- K5: per-(b,t) top-4 via parallel rank ----------------
// grid (TT/4, BB), block (64, 4). rank[e] = #{v_j > v_e} + #{j<e : v_j == v_e}
// -> stable descending order, identical to lax.top_k tie-breaking.
__global__ __launch_bounds__(256) void k_weights(const float* __restrict__ pb,
                                                 const float* __restrict__ pd,
                                                 const float* __restrict__ gamma) {
    int e = threadIdx.x;
    int ty = threadIdx.y;
    int t = blockIdx.x * 4 + ty;
    int b = blockIdx.y;

    __shared__ float s_log[4][EE];
    __shared__ float s_val[4][4];
    __shared__ int s_ix[4][4];

    float invHs = 1.f / fmaxf(__uint_as_float(g_Hbits), EPS_V);
    float invDs = 1.f / fmaxf(__uint_as_float(g_Dbits), EPS_V);

    float v = 0.5f * (pb[t * HH + e] + g_cond[b * EE + e]) * invHs +
              0.5f * pd[t * HH + e] * invDs;
    s_log[ty][e] = v;
    __syncthreads();

    int rank = 0;
#pragma unroll
    for (int j = 0; j < EE; ++j) {
        float u = s_log[ty][j];
        rank += (u > v) || (u == v && j < e);
    }
    if (rank < 4) {
        s_val[ty][rank] = v;
        s_ix[ty][rank] = e;
    }
    __syncthreads();

    if (e == 0) {
        float bv0 = s_val[ty][0], bv1 = s_val[ty][1];
        float bv2 = s_val[ty][2], bv3 = s_val[ty][3];
        float e1 = __expf(bv1 - bv0);
        float e2 = __expf(bv2 - bv0);
        float e3 = __expf(bv3 - bv0);
        float g = 1.f / (1.f + __expf(-gamma[0]));
        float scale = (1.f - g) / (1.0f + e1 + e2 + e3);
        g_w[b * TT + t] = make_float4(scale, e1 * scale, e2 * scale, e3 * scale);
        g_idx[b * TT + t] = make_int4(s_ix[ty][0], s_ix[ty][1], s_ix[ty][2], s_ix[ty][3]);
    }
}

// ---------------- K6: output, float2-vectorized, smem-staged experts ----------------
// grid (HH/CHUNK, BB, TSPLIT), block 128 (thread owns 2 consecutive h).
// smem 68 KB -> 3 blocks/SM. Gathers are LDS.64 conflict-free; stores __stcs
// (streaming, keeps g_pbpd L2-resident); pbpd loads batched 8-deep.
__global__ __launch_bounds__(128) void k_out2(const float* __restrict__ limes,
                                              const float* __restrict__ shv,
                                              const float* __restrict__ gamma,
                                              float* __restrict__ out) {
    extern __shared__ float sm[];
    float2* s_lime = (float2*)sm;                      // 64 x 128 float2 = 64 KB
    float4* s_w = (float4*)(sm + EE * CHUNK);          // 128 * 16B = 2 KB
    int4* s_i = (int4*)(s_w + THALF);                  // 128 * 16B = 2 KB

    int chunk = blockIdx.x, b = blockIdx.y, ts = blockIdx.z;
    int tid = threadIdx.x;
    int base = chunk * CHUNK;
    int tbase = ts * THALF;

#pragma unroll
    for (int e = 0; e < EE; ++e)
        s_lime[e * 128 + tid] = ((const float2*)(limes + (size_t)e * HH + base))[tid];
    s_w[tid] = g_w[b * TT + tbase + tid];
    s_i[tid] = g_idx[b * TT + tbase + tid];

    float g = 1.f / (1.f + __expf(-gamma[0]));
    float2 sh2 = ((const float2*)(shv + base))[tid];
    float gshx = g * sh2.x, gshy = g * sh2.y;
    __syncthreads();

    const float2* P = ((const float2*)(g_pbpd + (size_t)tbase * HH + base)) + tid;
    float2* O = ((float2*)(out + ((size_t)b * TT + tbase) * HH + base)) + tid;

    for (int t0 = 0; t0 < THALF; t0 += 8) {
        float2 p[8];
#pragma unroll
        for (int j = 0; j < 8; ++j) p[j] = P[(size_t)(t0 + j) * (HH / 2)];
#pragma unroll
        for (int j = 0; j < 8; ++j) {
            float4 w = s_w[t0 + j];
            int4 ix = s_i[t0 + j];
            float2 a = s_lime[ix.x * 128 + tid];
            float2 c = s_lime[ix.y * 128 + tid];
            float2 d = s_lime[ix.z * 128 + tid];
            float2 f = s_lime[ix.w * 128 + tid];
            float mx = gshx + w.x * a.x + w.y * c.x + w.z * d.x + w.w * f.x;
            float my = gshy + w.x * a.y + w.y * c.y + w.z * d.y + w.w * f.y;
            __stcs(O + (size_t)(t0 + j) * (HH / 2), make_float2(p[j].x * mx, p[j].y * my));
        }
    }
}

extern "C" void kernel_launch(void* const* d_in, const int* in_sizes, int n_in,
                              void* d_out, int out_size) {
    const float* x     = (const float*)d_in[0];  // input_embeds (B,S,H)
    const float* pb    = (const float*)d_in[1];  // prompt_base  (T,H)
    const float* pd    = (const float*)d_in[2];  // prompt_delta (T,H)
    const float* limes = (const float*)d_in[3];  // LiMEs        (E,H)
    const float* shv   = (const float*)d_in[4];  // LiME_shared  (H,)
    const float* gamma = (const float*)d_in[5];  // gamma        (1,)
    const float* W     = (const float*)d_in[6];  // W_proj       (H,H)
    float* out = (float*)d_out;                  // (B,T,H) f32

    static bool attr_set = false;
    if (!attr_set) {
        cudaFuncSetAttribute(k_out2, cudaFuncAttributeMaxDynamicSharedMemorySize, SMEM_OUT2);
        attr_set = true;
    }

    k_reduce_s<<<dim3(HH / 256, BB), 256>>>(x);
    k_pbpd<<<TT * HH / 1024, 256>>>(pb, pd);
    k_cond<<<dim3(EE, BB / 2), 256>>>(W);
    k_scales<<<256, 256>>>(pb, pd);
    k_weights<<<dim3(TT / 4, BB), dim3(64, 4)>>>(pb, pd, gamma);
    k_out2<<<dim3(HH / CHUNK, BB, TSPLIT), 128, SMEM_OUT2>>>(limes, shv, gamma, out);
}

// round 9
// speedup vs baseline: 2.4450x; 1.2083x over previous
#include <cuda_runtime.h>
#include <math.h>

#define BB 32
#define SS 256
#define TT 256
#define HH 4096
#define EE 64
#define EPS_V 1e-6f
#define CHUNK 128      // h per k_out2 block
#define TTILE 8        // t per k_out2 block

// ---------------- scratch (no allocations allowed) ----------------
__device__ float g_m[BB * HH];        // sum over s of input_embeds  (512 KB)
__device__ float g_cond[BB * EE];     // cond[:, :E]                 (8 KB)
__device__ float g_pbpd[TT * HH];     // prompt_base + prompt_delta  (4 MB)
__device__ float4 g_w[BB * TT];       // top-4 weights, pre-scaled by (1-g)
__device__ int4 g_idx[BB * TT];       // top-4 expert indices
__device__ unsigned int g_Hbits;      // max|H_slice| as uint bits
__device__ unsigned int g_Dbits;      // max|d_slice| as uint bits

// ---------------- K1: m[b,h] = sum_s x[b,s,h] ----------------
__global__ __launch_bounds__(256) void k_reduce_s(const float* __restrict__ x) {
    int b = blockIdx.y;
    int h = blockIdx.x * 256 + threadIdx.x;
    const float* p = x + (size_t)b * SS * HH + h;
    float acc = 0.f;
#pragma unroll 16
    for (int s = 0; s < SS; ++s) acc += p[(size_t)s * HH];
    g_m[b * HH + h] = acc;
}

// ---------------- K2: pbpd = pb + pd (float4); also resets max scalars ----------------
__global__ __launch_bounds__(256) void k_pbpd(const float* __restrict__ pb,
                                              const float* __restrict__ pd) {
    if (blockIdx.x == 0 && threadIdx.x == 0) {
        g_Hbits = 0u;
        g_Dbits = 0u;
    }
    int i = blockIdx.x * 256 + threadIdx.x;
    float4 a = ((const float4*)pb)[i];
    float4 c = ((const float4*)pd)[i];
    ((float4*)g_pbpd)[i] = make_float4(a.x + c.x, a.y + c.y, a.z + c.z, a.w + c.w);
}

// ---------------- K3: cond[b,e] = (1/S) * sum_h m[b,h]*W[e,h], e < E ----------------
// grid (EE, BB/2), block 256. 2 batch rows per block; W row via L2 (shared by 16 blocks).
__global__ __launch_bounds__(256) void k_cond(const float* __restrict__ W) {
    int e = blockIdx.x;
    int bg = blockIdx.y * 2;
    int tid = threadIdx.x;
    const float4* w = (const float4*)(W + (size_t)e * HH);
    const float4* m0 = (const float4*)(g_m + (size_t)bg * HH);
    const float4* m1 = (const float4*)(g_m + (size_t)(bg + 1) * HH);

    float a0 = 0.f, a1 = 0.f;
#pragma unroll
    for (int i = tid; i < HH / 4; i += 256) {
        float4 wv = __ldg(w + i);
        float4 v0 = m0[i];
        float4 v1 = m1[i];
        a0 += wv.x * v0.x + wv.y * v0.y + wv.z * v0.z + wv.w * v0.w;
        a1 += wv.x * v1.x + wv.y * v1.y + wv.z * v1.z + wv.w * v1.w;
    }
#pragma unroll
    for (int o = 16; o > 0; o >>= 1) {
        a0 += __shfl_down_sync(0xffffffffu, a0, o);
        a1 += __shfl_down_sync(0xffffffffu, a1, o);
    }
    __shared__ float sred[2][8];
    int warp = tid >> 5, lane = tid & 31;
    if (lane == 0) {
        sred[0][warp] = a0;
        sred[1][warp] = a1;
    }
    __syncthreads();
    if (tid < 2) {
        float v = 0.f;
#pragma unroll
        for (int j = 0; j < 8; ++j) v += sred[tid][j];
        g_cond[(bg + tid) * EE + e] = v * (1.0f / SS);
    }
}

// ---------------- K4: global scales, decomposed ----------------
// max_b |pb_te + c_be| = max(pb_te + cmax_e, -(pb_te + cmin_e)).
// grid 32, block 256: thread = (trow = tid>>6, e = tid&63); 8 t-rows per block.
__global__ __launch_bounds__(256) void k_scales(const float* __restrict__ pb,
                                                const float* __restrict__ pd) {
    __shared__ float s_cmax[EE], s_cmin[EE];
    int tid = threadIdx.x;
    if (tid < EE) {
        float cmx = -3.4e38f, cmn = 3.4e38f;
#pragma unroll
        for (int b = 0; b < BB; ++b) {
            float c = g_cond[b * EE + tid];
            cmx = fmaxf(cmx, c);
            cmn = fminf(cmn, c);
        }
        s_cmax[tid] = cmx;
        s_cmin[tid] = cmn;
    }
    __syncthreads();

    int e = tid & 63;
    int trow = tid >> 6;                 // 0..3
    float cmx = s_cmax[e], cmn = s_cmin[e];
    float hmax = 0.f, dmax = 0.f;
#pragma unroll
    for (int k = 0; k < 2; ++k) {
        int t = blockIdx.x * 8 + k * 4 + trow;
        float p = pb[t * HH + e];
        hmax = fmaxf(hmax, fmaxf(p + cmx, -(p + cmn)));
        dmax = fmaxf(dmax, fabsf(pd[t * HH + e]));
    }
#pragma unroll
    for (int o = 16; o > 0; o >>= 1) {
        hmax = fmaxf(hmax, __shfl_down_sync(0xffffffffu, hmax, o));
        dmax = fmaxf(dmax, __shfl_down_sync(0xffffffffu, dmax, o));
    }
    __shared__ float shm[8], sdm[8];
    if ((tid & 31) == 0) {
        shm[tid >> 5] = hmax;
        sdm[tid >> 5] = dmax;
    }
    __syncthreads();
    if (tid == 0) {
        float hv = shm[0], dv = sdm[0];
#pragma unroll
        for (int j = 1; j < 8; ++j) {
            hv = fmaxf(hv, shm[j]);
            dv = fmaxf(dv, sdm[j]);
        }
        atomicMax(&g_Hbits, __float_as_uint(hv));
        atomicMax(&g_Dbits, __float_as_uint(dv));
    }
}

// ---------------- K5: per-(b,t) top-4 via parallel rank ----------------
// grid (TT/4, BB), block (64, 4). rank[e] = #{v_j > v_e} + #{j<e : v_j == v_e}
// -> stable descending order, identical to lax.top_k tie-breaking.
__global__ __launch_bounds__(256) void k_weights(const float* __restrict__ pb,
                                                 const float* __restrict__ pd,
                                                 const float* __restrict__ gamma) {
    int e = threadIdx.x;
    int ty = threadIdx.y;
    int t = blockIdx.x * 4 + ty;
    int b = blockIdx.y;

    __shared__ float s_log[4][EE];
    __shared__ float s_val[4][4];
    __shared__ int s_ix[4][4];

    float invHs = 1.f / fmaxf(__uint_as_float(g_Hbits), EPS_V);
    float invDs = 1.f / fmaxf(__uint_as_float(g_Dbits), EPS_V);

    float v = 0.5f * (pb[t * HH + e] + g_cond[b * EE + e]) * invHs +
              0.5f * pd[t * HH + e] * invDs;
    s_log[ty][e] = v;
    __syncthreads();

    int rank = 0;
#pragma unroll
    for (int j = 0; j < EE; ++j) {
        float u = s_log[ty][j];
        rank += (u > v) || (u == v && j < e);
    }
    if (rank < 4) {
        s_val[ty][rank] = v;
        s_ix[ty][rank] = e;
    }
    __syncthreads();

    if (e == 0) {
        float bv0 = s_val[ty][0], bv1 = s_val[ty][1];
        float bv2 = s_val[ty][2], bv3 = s_val[ty][3];
        float e1 = __expf(bv1 - bv0);
        float e2 = __expf(bv2 - bv0);
        float e3 = __expf(bv3 - bv0);
        float g = 1.f / (1.f + __expf(-gamma[0]));
        float scale = (1.f - g) / (1.0f + e1 + e2 + e3);
        g_w[b * TT + t] = make_float4(scale, e1 * scale, e2 * scale, e3 * scale);
        g_idx[b * TT + t] = make_int4(s_ix[ty][0], s_ix[ty][1], s_ix[ty][2], s_ix[ty][3]);
    }
}

// ---------------- K6: output, b-inner loop, pbpd in registers ----------------
// grid (HH/CHUNK, TT/TTILE), block 64. Each block owns a (128-h x 8-t) output
// tile for ALL 32 batches. pbpd tile lives in registers (loaded once, reused
// 32x -> kills the 128 MB L2 p-stream). Experts for the chunk + the full
// (b x t-tile) weight table live in smem (40 KB -> 5 blocks/SM).
// Inner loop: pure LDS gather + FMA + __stcs, no load latency on critical path.
__global__ __launch_bounds__(64) void k_out2(const float* __restrict__ limes,
                                             const float* __restrict__ shv,
                                             const float* __restrict__ gamma,
                                             float* __restrict__ out) {
    __shared__ float2 s_lime[EE][CHUNK / 2];   // 64 x 64 float2 = 32 KB
    __shared__ float4 s_w[BB][TTILE];          // 4 KB
    __shared__ int4 s_i[BB][TTILE];            // 4 KB

    int chunk = blockIdx.x, ttile = blockIdx.y;
    int tid = threadIdx.x;                     // 0..63, owns float2 column
    int base = chunk * CHUNK;
    int tbase = ttile * TTILE;

    // stage experts (float4 loads, 32 iters/thread)
    for (int r = tid; r < EE * (CHUNK / 4); r += 64) {
        int e = r >> 5;                        // CHUNK/4 = 32 float4 per row
        int c = r & 31;
        float4 v = ((const float4*)(limes + (size_t)e * HH + base))[c];
        s_lime[e][2 * c] = make_float2(v.x, v.y);
        s_lime[e][2 * c + 1] = make_float2(v.z, v.w);
    }
    // stage weight table for all b
    for (int r = tid; r < BB * TTILE; r += 64) {
        int b = r >> 3, t = r & (TTILE - 1);
        s_w[b][t] = g_w[b * TT + tbase + t];
        s_i[b][t] = g_idx[b * TT + tbase + t];
    }

    // pbpd tile into registers (one-time L2 read)
    float2 p[TTILE];
#pragma unroll
    for (int j = 0; j < TTILE; ++j)
        p[j] = ((const float2*)(g_pbpd + (size_t)(tbase + j) * HH + base))[tid];

    float g = 1.f / (1.f + __expf(-gamma[0]));
    float2 sh2 = ((const float2*)(shv + base))[tid];
    float gshx = g * sh2.x, gshy = g * sh2.y;
    __syncthreads();

    for (int b = 0; b < BB; ++b) {
        float2* O = ((float2*)(out + ((size_t)b * TT + tbase) * HH + base)) + tid;
#pragma unroll
        for (int j = 0; j < TTILE; ++j) {
            float4 w = s_w[b][j];
            int4 ix = s_i[b][j];
            float2 a = s_lime[ix.x][tid];
            float2 c = s_lime[ix.y][tid];
            float2 d = s_lime[ix.z][tid];
            float2 f = s_lime[ix.w][tid];
            float mx = gshx + w.x * a.x + w.y * c.x + w.z * d.x + w.w * f.x;
            float my = gshy + w.x * a.y + w.y * c.y + w.z * d.y + w.w * f.y;
            __stcs(O + (size_t)j * (HH / 2), make_float2(p[j].x * mx, p[j].y * my));
        }
    }
}

extern "C" void kernel_launch(void* const* d_in, const int* in_sizes, int n_in,
                              void* d_out, int out_size) {
    const float* x     = (const float*)d_in[0];  // input_embeds (B,S,H)
    const float* pb    = (const float*)d_in[1];  // prompt_base  (T,H)
    const float* pd    = (const float*)d_in[2];  // prompt_delta (T,H)
    const float* limes = (const float*)d_in[3];  // LiMEs        (E,H)
    const float* shv   = (const float*)d_in[4];  // LiME_shared  (H,)
    const float* gamma = (const float*)d_in[5];  // gamma        (1,)
    const float* W     = (const float*)d_in[6];  // W_proj       (H,H)
    float* out = (float*)d_out;                  // (B,T,H) f32

    k_reduce_s<<<dim3(HH / 256, BB), 256>>>(x);
    k_pbpd<<<TT * HH / 1024, 256>>>(pb, pd);
    k_cond<<<dim3(EE, BB / 2), 256>>>(W);
    k_scales<<<32, 256>>>(pb, pd);
    k_weights<<<dim3(TT / 4, BB), dim3(64, 4)>>>(pb, pd, gamma);
    k_out2<<<dim3(HH / CHUNK, TT / TTILE), 64>>>(limes, shv, gamma, out);
}

// round 10
// speedup vs baseline: 2.4537x; 1.0035x over previous
#include <cuda_runtime.h>
#include <math.h>

#define BB 32
#define SS 256
#define TT 256
#define HH 4096
#define EE 64
#define EPS_V 1e-6f
#define CHUNK 128      // h per k_out2 block
#define TTILE 4        // t per k_out2 block

// ---------------- scratch (no allocations allowed) ----------------
__device__ float g_m[BB * HH];        // sum over s of input_embeds  (512 KB)
__device__ float g_cond[BB * EE];     // cond[:, :E]                 (8 KB)
__device__ float4 g_w[BB * TT];       // top-4 weights, pre-scaled by (1-g)
__device__ int4 g_idx[BB * TT];       // top-4 expert indices
__device__ float g_pbmax[EE];         // per-e max_t pb[t,e]
__device__ float g_pbmin[EE];         // per-e min_t pb[t,e]
__device__ float g_pdmax[EE];         // per-e max_t |pd[t,e]|
// (plain writes each run -> no resets, no atomics, fully deterministic)

// ---------------- K1: m[b,h] = sum_s x[b,s,h]  (+ hidden pb/pd stat block) ----------------
// grid (HH/256 + 1, BB). Block (16,0) computes per-e stats of pb/pd slices,
// fully hidden under the 134 MB x-read of the other 512 blocks.
__global__ __launch_bounds__(256) void k_reduce_s(const float* __restrict__ x,
                                                  const float* __restrict__ pb,
                                                  const float* __restrict__ pd) {
    int bx = blockIdx.x, b = blockIdx.y;
    int tid = threadIdx.x;

    if (bx == HH / 256) {
        if (b != 0) return;
        __shared__ float s_mx[4][EE], s_mn[4][EE], s_dm[4][EE];
        int e = tid & 63, q = tid >> 6;
        float mx = -3.4e38f, mn = 3.4e38f, dm = 0.f;
#pragma unroll 8
        for (int k = 0; k < 64; ++k) {
            int t = q * 64 + k;
            float p = pb[t * HH + e];
            float d = pd[t * HH + e];
            mx = fmaxf(mx, p);
            mn = fminf(mn, p);
            dm = fmaxf(dm, fabsf(d));
        }
        s_mx[q][e] = mx; s_mn[q][e] = mn; s_dm[q][e] = dm;
        __syncthreads();
        if (q == 0) {
#pragma unroll
            for (int j = 1; j < 4; ++j) {
                mx = fmaxf(mx, s_mx[j][e]);
                mn = fminf(mn, s_mn[j][e]);
                dm = fmaxf(dm, s_dm[j][e]);
            }
            g_pbmax[e] = mx;
            g_pbmin[e] = mn;
            g_pdmax[e] = dm;
        }
        return;
    }

    int h = bx * 256 + tid;
    const float* p = x + (size_t)b * SS * HH + h;
    float acc = 0.f;
#pragma unroll 16
    for (int s = 0; s < SS; ++s) acc += p[(size_t)s * HH];
    g_m[b * HH + h] = acc;
}

// ---------------- K2: cond[b,e] = (1/S) * sum_h m[b,h]*W[e,h], e < E ----------------
// grid (EE, BB/2), block 256. 2 batch rows per block; W row via L2 (shared by 16 blocks).
__global__ __launch_bounds__(256) void k_cond(const float* __restrict__ W) {
    int e = blockIdx.x;
    int bg = blockIdx.y * 2;
    int tid = threadIdx.x;
    const float4* w = (const float4*)(W + (size_t)e * HH);
    const float4* m0 = (const float4*)(g_m + (size_t)bg * HH);
    const float4* m1 = (const float4*)(g_m + (size_t)(bg + 1) * HH);

    float a0 = 0.f, a1 = 0.f;
#pragma unroll
    for (int i = tid; i < HH / 4; i += 256) {
        float4 wv = __ldg(w + i);
        float4 v0 = m0[i];
        float4 v1 = m1[i];
        a0 += wv.x * v0.x + wv.y * v0.y + wv.z * v0.z + wv.w * v0.w;
        a1 += wv.x * v1.x + wv.y * v1.y + wv.z * v1.z + wv.w * v1.w;
    }
#pragma unroll
    for (int o = 16; o > 0; o >>= 1) {
        a0 += __shfl_down_sync(0xffffffffu, a0, o);
        a1 += __shfl_down_sync(0xffffffffu, a1, o);
    }
    __shared__ float sred[2][8];
    int warp = tid >> 5, lane = tid & 31;
    if (lane == 0) {
        sred[0][warp] = a0;
        sred[1][warp] = a1;
    }
    __syncthreads();
    if (tid < 2) {
        float v = 0.f;
#pragma unroll
        for (int j = 0; j < 8; ++j) v += sred[tid][j];
        g_cond[(bg + tid) * EE + e] = v * (1.0f / SS);
    }
}

// ---------------- K3: scales (recomputed per block, exact) + top-4 + weights ----------------
// grid (TT/4, BB), block (64, 4).
// H_scale = max_e max(pbmax_e + max_b c_be, -(pbmin_e + min_b c_be)) -- exact
// decomposition of max_{b,t,e}|pb+c| since pb depends only on t, c only on b.
// rank[e] = #{v_j > v_e} + #{j<e: v_j == v_e} -> stable order == lax.top_k.
__global__ __launch_bounds__(256) void k_weights(const float* __restrict__ pb,
                                                 const float* __restrict__ pd,
                                                 const float* __restrict__ gamma) {
    int e = threadIdx.x;   // 0..63
    int ty = threadIdx.y;  // 0..3
    int t = blockIdx.x * 4 + ty;
    int b = blockIdx.y;

    __shared__ float s_cmx[4][EE], s_cmn[4][EE];
    __shared__ float s_h[EE], s_d[EE];
    __shared__ float s_scl[2];
    __shared__ float s_log[4][EE];
    __shared__ float s_val[4][4];
    __shared__ int s_ix[4][4];

    // phase 0: global scales from per-e stats (L2-resident scalars)
    {
        float cmx = -3.4e38f, cmn = 3.4e38f;
#pragma unroll
        for (int j = 0; j < 8; ++j) {
            float c = g_cond[(ty * 8 + j) * EE + e];
            cmx = fmaxf(cmx, c);
            cmn = fminf(cmn, c);
        }
        s_cmx[ty][e] = cmx;
        s_cmn[ty][e] = cmn;
        __syncthreads();
        if (ty == 0) {
#pragma unroll
            for (int j = 1; j < 4; ++j) {
                cmx = fmaxf(cmx, s_cmx[j][e]);
                cmn = fminf(cmn, s_cmn[j][e]);
            }
            s_h[e] = fmaxf(g_pbmax[e] + cmx, -(g_pbmin[e] + cmn));
            s_d[e] = g_pdmax[e];
        }
        __syncthreads();
        if (ty == 0 && e < 32) {
            float hv = fmaxf(s_h[e], s_h[e + 32]);
            float dv = fmaxf(s_d[e], s_d[e + 32]);
#pragma unroll
            for (int o = 16; o > 0; o >>= 1) {
                hv = fmaxf(hv, __shfl_down_sync(0xffffffffu, hv, o));
                dv = fmaxf(dv, __shfl_down_sync(0xffffffffu, dv, o));
            }
            if (e == 0) {
                s_scl[0] = 1.f / fmaxf(hv, EPS_V);
                s_scl[1] = 1.f / fmaxf(dv, EPS_V);
            }
        }
        __syncthreads();
    }
    float invHs = s_scl[0], invDs = s_scl[1];

    // phase 1: logits + parallel rank + weights
    float v = 0.5f * (pb[t * HH + e] + g_cond[b * EE + e]) * invHs +
              0.5f * pd[t * HH + e] * invDs;
    s_log[ty][e] = v;
    __syncthreads();

    int rank = 0;
#pragma unroll
    for (int j = 0; j < EE; ++j) {
        float u = s_log[ty][j];
        rank += (u > v) || (u == v && j < e);
    }
    if (rank < 4) {
        s_val[ty][rank] = v;
        s_ix[ty][rank] = e;
    }
    __syncthreads();

    if (e == 0) {
        float bv0 = s_val[ty][0], bv1 = s_val[ty][1];
        float bv2 = s_val[ty][2], bv3 = s_val[ty][3];
        float e1 = __expf(bv1 - bv0);
        float e2 = __expf(bv2 - bv0);
        float e3 = __expf(bv3 - bv0);
        float g = 1.f / (1.f + __expf(-gamma[0]));
        float scale = (1.f - g) / (1.0f + e1 + e2 + e3);
        g_w[b * TT + t] = make_float4(scale, e1 * scale, e2 * scale, e3 * scale);
        g_idx[b * TT + t] = make_int4(s_ix[ty][0], s_ix[ty][1], s_ix[ty][2], s_ix[ty][3]);
    }
}

// ---------------- K4: output, b-inner loop, pb+pd tile in registers ----------------
// grid (HH/CHUNK, TT/TTILE) = (32, 64), block 64. Each block owns a
// (128-h x 4-t) output tile for ALL 32 batches. pbpd tile computed on the fly
// from pb+pd (read once, reused 32x). smem 36 KB -> 6 blocks/SM, 12 warps/SM,
// 2048 blocks -> smooth waves. Inner loop: LDS gather + FMA + __stcs only.
__global__ __launch_bounds__(64) void k_out2(const float* __restrict__ pb,
                                             const float* __restrict__ pd,
                                             const float* __restrict__ limes,
                                             const float* __restrict__ shv,
                                             const float* __restrict__ gamma,
                                             float* __restrict__ out) {
    __shared__ float2 s_lime[EE][CHUNK / 2];   // 64 x 64 float2 = 32 KB
    __shared__ float4 s_w[BB][TTILE];          // 2 KB
    __shared__ int4 s_i[BB][TTILE];            // 2 KB

    int chunk = blockIdx.x, ttile = blockIdx.y;
    int tid = threadIdx.x;                     // 0..63, owns float2 column
    int base = chunk * CHUNK;
    int tbase = ttile * TTILE;

    // stage experts (float4 loads)
    for (int r = tid; r < EE * (CHUNK / 4); r += 64) {
        int e = r >> 5;                        // CHUNK/4 = 32 float4 per row
        int c = r & 31;
        float4 v = ((const float4*)(limes + (size_t)e * HH + base))[c];
        s_lime[e][2 * c] = make_float2(v.x, v.y);
        s_lime[e][2 * c + 1] = make_float2(v.z, v.w);
    }
    // stage weight table for all b
    for (int r = tid; r < BB * TTILE; r += 64) {
        int b = r >> 2, t = r & (TTILE - 1);
        s_w[b][t] = g_w[b * TT + tbase + t];
        s_i[b][t] = g_idx[b * TT + tbase + t];
    }

    // pb+pd tile into registers (one-time read, reused for all 32 b)
    float2 p[TTILE];
#pragma unroll
    for (int j = 0; j < TTILE; ++j) {
        float2 a = ((const float2*)(pb + (size_t)(tbase + j) * HH + base))[tid];
        float2 c = ((const float2*)(pd + (size_t)(tbase + j) * HH + base))[tid];
        p[j] = make_float2(a.x + c.x, a.y + c.y);
    }

    float g = 1.f / (1.f + __expf(-gamma[0]));
    float2 sh2 = ((const float2*)(shv + base))[tid];
    float gshx = g * sh2.x, gshy = g * sh2.y;
    __syncthreads();

    for (int b = 0; b < BB; ++b) {
        float2* O = ((float2*)(out + ((size_t)b * TT + tbase) * HH + base)) + tid;
#pragma unroll
        for (int j = 0; j < TTILE; ++j) {
            float4 w = s_w[b][j];
            int4 ix = s_i[b][j];
            float2 a = s_lime[ix.x][tid];
            float2 c = s_lime[ix.y][tid];
            float2 d = s_lime[ix.z][tid];
            float2 f = s_lime[ix.w][tid];
            float mx = gshx + w.x * a.x + w.y * c.x + w.z * d.x + w.w * f.x;
            float my = gshy + w.x * a.y + w.y * c.y + w.z * d.y + w.w * f.y;
            __stcs(O + (size_t)j * (HH / 2), make_float2(p[j].x * mx, p[j].y * my));
        }
    }
}

extern "C" void kernel_launch(void* const* d_in, const int* in_sizes, int n_in,
                              void* d_out, int out_size) {
    const float* x     = (const float*)d_in[0];  // input_embeds (B,S,H)
    const float* pb    = (const float*)d_in[1];  // prompt_base  (T,H)
    const float* pd    = (const float*)d_in[2];  // prompt_delta (T,H)
    const float* limes = (const float*)d_in[3];  // LiMEs        (E,H)
    const float* shv   = (const float*)d_in[4];  // LiME_shared  (H,)
    const float* gamma = (const float*)d_in[5];  // gamma        (1,)
    const float* W     = (const float*)d_in[6];  // W_proj       (H,H)
    float* out = (float*)d_out;                  // (B,T,H) f32

    k_reduce_s<<<dim3(HH / 256 + 1, BB), 256>>>(x, pb, pd);
    k_cond<<<dim3(EE, BB / 2), 256>>>(W);
    k_weights<<<dim3(TT / 4, BB), dim3(64, 4)>>>(pb, pd, gamma);
    k_out2<<<dim3(HH / CHUNK, TT / TTILE), 64>>>(pb, pd, limes, shv, gamma, out);
}

// round 11
// speedup vs baseline: 2.6311x; 1.0723x over previous
#include <cuda_runtime.h>
#include <cuda_fp16.h>
#include <math.h>

#define BB 32
#define SS 256
#define TT 256
#define HH 4096
#define EE 64
#define EPS_V 1e-6f
#define CHUNK 256      // h per k_out2 block (128 half2 columns)
#define TTILE 2        // t per k_out2 block

// ---------------- scratch (no allocations allowed) ----------------
__device__ float g_m[BB * HH];        // sum over s of input_embeds  (512 KB)
__device__ float g_cond[BB * EE];     // cond[:, :E]                 (8 KB)
__device__ float4 g_w[BB * TT];       // top-4 weights, pre-scaled by (1-g)
__device__ int4 g_idx[BB * TT];       // top-4 expert indices
__device__ float g_pbmax[EE];         // per-e max_t pb[t,e]
__device__ float g_pbmin[EE];         // per-e min_t pb[t,e]
__device__ float g_pdmax[EE];         // per-e max_t |pd[t,e]|
// (plain writes each run -> no resets, no atomics, fully deterministic)

// ---------------- K1: m[b,h] = sum_s x[b,s,h]  (+ hidden pb/pd stat block) ----------------
__global__ __launch_bounds__(256) void k_reduce_s(const float* __restrict__ x,
                                                  const float* __restrict__ pb,
                                                  const float* __restrict__ pd) {
    int bx = blockIdx.x, b = blockIdx.y;
    int tid = threadIdx.x;

    if (bx == HH / 256) {
        if (b != 0) return;
        __shared__ float s_mx[4][EE], s_mn[4][EE], s_dm[4][EE];
        int e = tid & 63, q = tid >> 6;
        float mx = -3.4e38f, mn = 3.4e38f, dm = 0.f;
#pragma unroll 8
        for (int k = 0; k < 64; ++k) {
            int t = q * 64 + k;
            float p = pb[t * HH + e];
            float d = pd[t * HH + e];
            mx = fmaxf(mx, p);
            mn = fminf(mn, p);
            dm = fmaxf(dm, fabsf(d));
        }
        s_mx[q][e] = mx; s_mn[q][e] = mn; s_dm[q][e] = dm;
        __syncthreads();
        if (q == 0) {
#pragma unroll
            for (int j = 1; j < 4; ++j) {
                mx = fmaxf(mx, s_mx[j][e]);
                mn = fminf(mn, s_mn[j][e]);
                dm = fmaxf(dm, s_dm[j][e]);
            }
            g_pbmax[e] = mx;
            g_pbmin[e] = mn;
            g_pdmax[e] = dm;
        }
        return;
    }

    int h = bx * 256 + tid;
    const float* p = x + (size_t)b * SS * HH + h;
    float acc = 0.f;
#pragma unroll 16
    for (int s = 0; s < SS; ++s) acc += p[(size_t)s * HH];
    g_m[b * HH + h] = acc;
}

// ---------------- K2: cond[b,e] = (1/S) * sum_h m[b,h]*W[e,h], e < E ----------------
__global__ __launch_bounds__(256) void k_cond(const float* __restrict__ W) {
    int e = blockIdx.x;
    int bg = blockIdx.y * 2;
    int tid = threadIdx.x;
    const float4* w = (const float4*)(W + (size_t)e * HH);
    const float4* m0 = (const float4*)(g_m + (size_t)bg * HH);
    const float4* m1 = (const float4*)(g_m + (size_t)(bg + 1) * HH);

    float a0 = 0.f, a1 = 0.f;
#pragma unroll
    for (int i = tid; i < HH / 4; i += 256) {
        float4 wv = __ldg(w + i);
        float4 v0 = m0[i];
        float4 v1 = m1[i];
        a0 += wv.x * v0.x + wv.y * v0.y + wv.z * v0.z + wv.w * v0.w;
        a1 += wv.x * v1.x + wv.y * v1.y + wv.z * v1.z + wv.w * v1.w;
    }
#pragma unroll
    for (int o = 16; o > 0; o >>= 1) {
        a0 += __shfl_down_sync(0xffffffffu, a0, o);
        a1 += __shfl_down_sync(0xffffffffu, a1, o);
    }
    __shared__ float sred[2][8];
    int warp = tid >> 5, lane = tid & 31;
    if (lane == 0) {
        sred[0][warp] = a0;
        sred[1][warp] = a1;
    }
    __syncthreads();
    if (tid < 2) {
        float v = 0.f;
#pragma unroll
        for (int j = 0; j < 8; ++j) v += sred[tid][j];
        g_cond[(bg + tid) * EE + e] = v * (1.0f / SS);
    }
}

// ---------------- K3: scales (exact decomposition) + top-4 + weights ----------------
__global__ __launch_bounds__(256) void k_weights(const float* __restrict__ pb,
                                                 const float* __restrict__ pd,
                                                 const float* __restrict__ gamma) {
    int e = threadIdx.x;   // 0..63
    int ty = threadIdx.y;  // 0..3
    int t = blockIdx.x * 4 + ty;
    int b = blockIdx.y;

    __shared__ float s_cmx[4][EE], s_cmn[4][EE];
    __shared__ float s_h[EE], s_d[EE];
    __shared__ float s_scl[2];
    __shared__ float s_log[4][EE];
    __shared__ float s_val[4][4];
    __shared__ int s_ix[4][4];

    {
        float cmx = -3.4e38f, cmn = 3.4e38f;
#pragma unroll
        for (int j = 0; j < 8; ++j) {
            float c = g_cond[(ty * 8 + j) * EE + e];
            cmx = fmaxf(cmx, c);
            cmn = fminf(cmn, c);
        }
        s_cmx[ty][e] = cmx;
        s_cmn[ty][e] = cmn;
        __syncthreads();
        if (ty == 0) {
#pragma unroll
            for (int j = 1; j < 4; ++j) {
                cmx = fmaxf(cmx, s_cmx[j][e]);
                cmn = fminf(cmn, s_cmn[j][e]);
            }
            s_h[e] = fmaxf(g_pbmax[e] + cmx, -(g_pbmin[e] + cmn));
            s_d[e] = g_pdmax[e];
        }
        __syncthreads();
        if (ty == 0 && e < 32) {
            float hv = fmaxf(s_h[e], s_h[e + 32]);
            float dv = fmaxf(s_d[e], s_d[e + 32]);
#pragma unroll
            for (int o = 16; o > 0; o >>= 1) {
                hv = fmaxf(hv, __shfl_down_sync(0xffffffffu, hv, o));
                dv = fmaxf(dv, __shfl_down_sync(0xffffffffu, dv, o));
            }
            if (e == 0) {
                s_scl[0] = 1.f / fmaxf(hv, EPS_V);
                s_scl[1] = 1.f / fmaxf(dv, EPS_V);
            }
        }
        __syncthreads();
    }
    float invHs = s_scl[0], invDs = s_scl[1];

    float v = 0.5f * (pb[t * HH + e] + g_cond[b * EE + e]) * invHs +
              0.5f * pd[t * HH + e] * invDs;
    s_log[ty][e] = v;
    __syncthreads();

    int rank = 0;
#pragma unroll
    for (int j = 0; j < EE; ++j) {
        float u = s_log[ty][j];
        rank += (u > v) || (u == v && j < e);
    }
    if (rank < 4) {
        s_val[ty][rank] = v;
        s_ix[ty][rank] = e;
    }
    __syncthreads();

    if (e == 0) {
        float bv0 = s_val[ty][0], bv1 = s_val[ty][1];
        float bv2 = s_val[ty][2], bv3 = s_val[ty][3];
        float e1 = __expf(bv1 - bv0);
        float e2 = __expf(bv2 - bv0);
        float e3 = __expf(bv3 - bv0);
        float g = 1.f / (1.f + __expf(-gamma[0]));
        float scale = (1.f - g) / (1.0f + e1 + e2 + e3);
        g_w[b * TT + t] = make_float4(scale, e1 * scale, e2 * scale, e3 * scale);
        g_idx[b * TT + t] = make_int4(s_ix[ty][0], s_ix[ty][1], s_ix[ty][2], s_ix[ty][3]);
    }
}

// ---------------- K4: output, fp16 residual experts, half-width gathers ----------------
// LiMEs = 1 + u, |u|<=0.1; sum_k w_k = (1-g) exactly (renorm), so
//   mix = gsh + (w.x+w.y+w.z+w.w) + sum_k w_k*u_k
// with only u staged in smem as half2 (fp16 err on u ~5e-5 absolute -> ~5e-5
// final rel err). Gathers become LDS.32 (1 wavefront vs 2), expert smem halves
// -> CHUNK 256 with block 128: smem 34 KB -> 6 blocks/SM -> 24 warps (2x occ).
// grid (HH/CHUNK, TT/TTILE) = (16,128) = 2048 blocks -> 2.3 smooth waves.
__global__ __launch_bounds__(128) void k_out2(const float* __restrict__ pb,
                                              const float* __restrict__ pd,
                                              const float* __restrict__ limes,
                                              const float* __restrict__ shv,
                                              const float* __restrict__ gamma,
                                              float* __restrict__ out) {
    __shared__ __half2 s_u[EE][CHUNK / 2];     // 64 x 128 half2 = 32 KB
    __shared__ float4 s_w[BB][TTILE];          // 1 KB
    __shared__ int4 s_i[BB][TTILE];            // 1 KB

    int chunk = blockIdx.x, ttile = blockIdx.y;
    int tid = threadIdx.x;                     // 0..127, owns half2 column (2 h)
    int base = chunk * CHUNK;
    int tbase = ttile * TTILE;

    // stage residual experts u = lime - 1 as half2 (float4 loads, 32/thread)
    for (int r = tid; r < EE * (CHUNK / 4); r += 128) {
        int e = r >> 6;                        // CHUNK/4 = 64 float4 per row
        int c = r & 63;
        float4 v = ((const float4*)(limes + (size_t)e * HH + base))[c];
        s_u[e][2 * c] = __floats2half2_rn(v.x - 1.0f, v.y - 1.0f);
        s_u[e][2 * c + 1] = __floats2half2_rn(v.z - 1.0f, v.w - 1.0f);
    }
    // stage weight table for all b
    for (int r = tid; r < BB * TTILE; r += 128) {
        int b = r / TTILE, t = r % TTILE;
        s_w[b][t] = g_w[b * TT + tbase + t];
        s_i[b][t] = g_idx[b * TT + tbase + t];
    }

    // pb+pd tile into registers (one-time read, reused for all 32 b)
    float2 p[TTILE];
#pragma unroll
    for (int j = 0; j < TTILE; ++j) {
        float2 a = ((const float2*)(pb + (size_t)(tbase + j) * HH + base))[tid];
        float2 c = ((const float2*)(pd + (size_t)(tbase + j) * HH + base))[tid];
        p[j] = make_float2(a.x + c.x, a.y + c.y);
    }

    float g = 1.f / (1.f + __expf(-gamma[0]));
    float2 sh2 = ((const float2*)(shv + base))[tid];
    float gshx = g * sh2.x, gshy = g * sh2.y;
    __syncthreads();

    for (int b = 0; b < BB; ++b) {
        float2* O = ((float2*)(out + ((size_t)b * TT + tbase) * HH + base)) + tid;
#pragma unroll
        for (int j = 0; j < TTILE; ++j) {
            float4 w = s_w[b][j];
            int4 ix = s_i[b][j];
            float2 a = __half22float2(s_u[ix.x][tid]);
            float2 c = __half22float2(s_u[ix.y][tid]);
            float2 d = __half22float2(s_u[ix.z][tid]);
            float2 f = __half22float2(s_u[ix.w][tid]);
            float wsum = (w.x + w.y) + (w.z + w.w);
            float mx = (gshx + wsum) + w.x * a.x + w.y * c.x + w.z * d.x + w.w * f.x;
            float my = (gshy + wsum) + w.x * a.y + w.y * c.y + w.z * d.y + w.w * f.y;
            __stcs(O + (size_t)j * (HH / 2), make_float2(p[j].x * mx, p[j].y * my));
        }
    }
}

extern "C" void kernel_launch(void* const* d_in, const int* in_sizes, int n_in,
                              void* d_out, int out_size) {
    const float* x     = (const float*)d_in[0];  // input_embeds (B,S,H)
    const float* pb    = (const float*)d_in[1];  // prompt_base  (T,H)
    const float* pd    = (const float*)d_in[2];  // prompt_delta (T,H)
    const float* limes = (const float*)d_in[3];  // LiMEs        (E,H)
    const float* shv   = (const float*)d_in[4];  // LiME_shared  (H,)
    const float* gamma = (const float*)d_in[5];  // gamma        (1,)
    const float* W     = (const float*)d_in[6];  // W_proj       (H,H)
    float* out = (float*)d_out;                  // (B,T,H) f32

    k_reduce_s<<<dim3(HH / 256 + 1, BB), 256>>>(x, pb, pd);
    k_cond<<<dim3(EE, BB / 2), 256>>>(W);
    k_weights<<<dim3(TT / 4, BB), dim3(64, 4)>>>(pb, pd, gamma);
    k_out2<<<dim3(HH / CHUNK, TT / TTILE), 128>>>(pb, pd, limes, shv, gamma, out);
}

// round 12
// speedup vs baseline: 2.6843x; 1.0202x over previous
#include <cuda_runtime.h>
#include <cuda_fp16.h>
#include <math.h>

#define BB 32
#define SS 256
#define TT 256
#define HH 4096
#define EE 64
#define EPS_V 1e-6f
#define CHUNK 256      // h per k_out2 block (128 half2 columns)
#define TTILE 8        // t per k_out2 block (staging amortization)

// ---------------- scratch (no allocations allowed) ----------------
__device__ float g_m[BB * HH];        // sum over s of input_embeds  (512 KB)
__device__ float g_cond[BB * EE];     // cond[:, :E]                 (8 KB)
__device__ float4 g_w[BB * TT];       // top-4 weights, pre-scaled by (1-g)
__device__ int4 g_idx[BB * TT];       // top-4 expert indices
__device__ float g_pbmax[EE];         // per-e max_t pb[t,e]
__device__ float g_pbmin[EE];         // per-e min_t pb[t,e]
__device__ float g_pdmax[EE];         // per-e max_t |pd[t,e]|
// (plain writes each run -> no resets, no atomics, fully deterministic)

// ---------------- K1: m[b,h] = sum_s x[b,s,h]  (+ hidden pb/pd stat block) ----------------
__global__ __launch_bounds__(256) void k_reduce_s(const float* __restrict__ x,
                                                  const float* __restrict__ pb,
                                                  const float* __restrict__ pd) {
    int bx = blockIdx.x, b = blockIdx.y;
    int tid = threadIdx.x;

    if (bx == HH / 256) {
        if (b != 0) return;
        __shared__ float s_mx[4][EE], s_mn[4][EE], s_dm[4][EE];
        int e = tid & 63, q = tid >> 6;
        float mx = -3.4e38f, mn = 3.4e38f, dm = 0.f;
#pragma unroll 8
        for (int k = 0; k < 64; ++k) {
            int t = q * 64 + k;
            float p = pb[t * HH + e];
            float d = pd[t * HH + e];
            mx = fmaxf(mx, p);
            mn = fminf(mn, p);
            dm = fmaxf(dm, fabsf(d));
        }
        s_mx[q][e] = mx; s_mn[q][e] = mn; s_dm[q][e] = dm;
        __syncthreads();
        if (q == 0) {
#pragma unroll
            for (int j = 1; j < 4; ++j) {
                mx = fmaxf(mx, s_mx[j][e]);
                mn = fminf(mn, s_mn[j][e]);
                dm = fmaxf(dm, s_dm[j][e]);
            }
            g_pbmax[e] = mx;
            g_pbmin[e] = mn;
            g_pdmax[e] = dm;
        }
        return;
    }

    int h = bx * 256 + tid;
    const float* p = x + (size_t)b * SS * HH + h;
    float acc = 0.f;
#pragma unroll 16
    for (int s = 0; s < SS; ++s) acc += p[(size_t)s * HH];
    g_m[b * HH + h] = acc;
}

// ---------------- K2: cond[b,e] = (1/S) * sum_h m[b,h]*W[e,h], e < E ----------------
__global__ __launch_bounds__(256) void k_cond(const float* __restrict__ W) {
    int e = blockIdx.x;
    int bg = blockIdx.y * 2;
    int tid = threadIdx.x;
    const float4* w = (const float4*)(W + (size_t)e * HH);
    const float4* m0 = (const float4*)(g_m + (size_t)bg * HH);
    const float4* m1 = (const float4*)(g_m + (size_t)(bg + 1) * HH);

    float a0 = 0.f, a1 = 0.f;
#pragma unroll
    for (int i = tid; i < HH / 4; i += 256) {
        float4 wv = __ldg(w + i);
        float4 v0 = m0[i];
        float4 v1 = m1[i];
        a0 += wv.x * v0.x + wv.y * v0.y + wv.z * v0.z + wv.w * v0.w;
        a1 += wv.x * v1.x + wv.y * v1.y + wv.z * v1.z + wv.w * v1.w;
    }
#pragma unroll
    for (int o = 16; o > 0; o >>= 1) {
        a0 += __shfl_down_sync(0xffffffffu, a0, o);
        a1 += __shfl_down_sync(0xffffffffu, a1, o);
    }
    __shared__ float sred[2][8];
    int warp = tid >> 5, lane = tid & 31;
    if (lane == 0) {
        sred[0][warp] = a0;
        sred[1][warp] = a1;
    }
    __syncthreads();
    if (tid < 2) {
        float v = 0.f;
#pragma unroll
        for (int j = 0; j < 8; ++j) v += sred[tid][j];
        g_cond[(bg + tid) * EE + e] = v * (1.0f / SS);
    }
}

// ---------------- K3: scales (exact decomposition) + top-4 + weights ----------------
__global__ __launch_bounds__(256) void k_weights(const float* __restrict__ pb,
                                                 const float* __restrict__ pd,
                                                 const float* __restrict__ gamma) {
    int e = threadIdx.x;   // 0..63
    int ty = threadIdx.y;  // 0..3
    int t = blockIdx.x * 4 + ty;
    int b = blockIdx.y;

    __shared__ float s_cmx[4][EE], s_cmn[4][EE];
    __shared__ float s_h[EE], s_d[EE];
    __shared__ float s_scl[2];
    __shared__ float s_log[4][EE];
    __shared__ float s_val[4][4];
    __shared__ int s_ix[4][4];

    {
        float cmx = -3.4e38f, cmn = 3.4e38f;
#pragma unroll
        for (int j = 0; j < 8; ++j) {
            float c = g_cond[(ty * 8 + j) * EE + e];
            cmx = fmaxf(cmx, c);
            cmn = fminf(cmn, c);
        }
        s_cmx[ty][e] = cmx;
        s_cmn[ty][e] = cmn;
        __syncthreads();
        if (ty == 0) {
#pragma unroll
            for (int j = 1; j < 4; ++j) {
                cmx = fmaxf(cmx, s_cmx[j][e]);
                cmn = fminf(cmn, s_cmn[j][e]);
            }
            s_h[e] = fmaxf(g_pbmax[e] + cmx, -(g_pbmin[e] + cmn));
            s_d[e] = g_pdmax[e];
        }
        __syncthreads();
        if (ty == 0 && e < 32) {
            float hv = fmaxf(s_h[e], s_h[e + 32]);
            float dv = fmaxf(s_d[e], s_d[e + 32]);
#pragma unroll
            for (int o = 16; o > 0; o >>= 1) {
                hv = fmaxf(hv, __shfl_down_sync(0xffffffffu, hv, o));
                dv = fmaxf(dv, __shfl_down_sync(0xffffffffu, dv, o));
            }
            if (e == 0) {
                s_scl[0] = 1.f / fmaxf(hv, EPS_V);
                s_scl[1] = 1.f / fmaxf(dv, EPS_V);
            }
        }
        __syncthreads();
    }
    float invHs = s_scl[0], invDs = s_scl[1];

    float v = 0.5f * (pb[t * HH + e] + g_cond[b * EE + e]) * invHs +
              0.5f * pd[t * HH + e] * invDs;
    s_log[ty][e] = v;
    __syncthreads();

    int rank = 0;
#pragma unroll
    for (int j = 0; j < EE; ++j) {
        float u = s_log[ty][j];
        rank += (u > v) || (u == v && j < e);
    }
    if (rank < 4) {
        s_val[ty][rank] = v;
        s_ix[ty][rank] = e;
    }
    __syncthreads();

    if (e == 0) {
        float bv0 = s_val[ty][0], bv1 = s_val[ty][1];
        float bv2 = s_val[ty][2], bv3 = s_val[ty][3];
        float e1 = __expf(bv1 - bv0);
        float e2 = __expf(bv2 - bv0);
        float e3 = __expf(bv3 - bv0);
        float g = 1.f / (1.f + __expf(-gamma[0]));
        float scale = (1.f - g) / (1.0f + e1 + e2 + e3);
        g_w[b * TT + t] = make_float4(scale, e1 * scale, e2 * scale, e3 * scale);
        g_idx[b * TT + t] = make_int4(s_ix[ty][0], s_ix[ty][1], s_ix[ty][2], s_ix[ty][3]);
    }
}

// ---------------- K4: output, fp16 residual experts, TTILE=8 staging amortization ----------------
// LiMEs = 1 + u, |u|<=0.1; sum_k w_k = (1-g) exactly, so
//   mix = gsh + (w.x+w.y+w.z+w.w) + sum_k w_k*u_k   (u staged as half2)
// TTILE=8: the 96 KB/block staging cost (expert chunk LDG+STS) now amortizes
// over 4x more output, dropping staging from 42% to 15% of L1 wavefronts.
// grid (16, 32) = 512 blocks -> all resident in one wave (~3.5/SM).
__global__ __launch_bounds__(128) void k_out2(const float* __restrict__ pb,
                                              const float* __restrict__ pd,
                                              const float* __restrict__ limes,
                                              const float* __restrict__ shv,
                                              const float* __restrict__ gamma,
                                              float* __restrict__ out) {
    __shared__ __half2 s_u[EE][CHUNK / 2];     // 64 x 128 half2 = 32 KB
    __shared__ float4 s_w[BB][TTILE];          // 4 KB
    __shared__ int4 s_i[BB][TTILE];            // 4 KB

    int chunk = blockIdx.x, ttile = blockIdx.y;
    int tid = threadIdx.x;                     // 0..127, owns half2 column (2 h)
    int base = chunk * CHUNK;
    int tbase = ttile * TTILE;

    // stage residual experts u = lime - 1 as half2 (float4 loads, 32/thread)
    for (int r = tid; r < EE * (CHUNK / 4); r += 128) {
        int e = r >> 6;                        // CHUNK/4 = 64 float4 per row
        int c = r & 63;
        float4 v = ((const float4*)(limes + (size_t)e * HH + base))[c];
        s_u[e][2 * c] = __floats2half2_rn(v.x - 1.0f, v.y - 1.0f);
        s_u[e][2 * c + 1] = __floats2half2_rn(v.z - 1.0f, v.w - 1.0f);
    }
    // stage weight table for all b x 8 t
    for (int r = tid; r < BB * TTILE; r += 128) {
        int b = r / TTILE, t = r % TTILE;
        s_w[b][t] = g_w[b * TT + tbase + t];
        s_i[b][t] = g_idx[b * TT + tbase + t];
    }

    // pb+pd tile into registers (one-time read, reused for all 32 b)
    float2 p[TTILE];
#pragma unroll
    for (int j = 0; j < TTILE; ++j) {
        float2 a = ((const float2*)(pb + (size_t)(tbase + j) * HH + base))[tid];
        float2 c = ((const float2*)(pd + (size_t)(tbase + j) * HH + base))[tid];
        p[j] = make_float2(a.x + c.x, a.y + c.y);
    }

    float g = 1.f / (1.f + __expf(-gamma[0]));
    float2 sh2 = ((const float2*)(shv + base))[tid];
    float gshx = g * sh2.x, gshy = g * sh2.y;
    __syncthreads();

    for (int b = 0; b < BB; ++b) {
        float2* O = ((float2*)(out + ((size_t)b * TT + tbase) * HH + base)) + tid;
#pragma unroll
        for (int j = 0; j < TTILE; ++j) {
            float4 w = s_w[b][j];
            int4 ix = s_i[b][j];
            float2 a = __half22float2(s_u[ix.x][tid]);
            float2 c = __half22float2(s_u[ix.y][tid]);
            float2 d = __half22float2(s_u[ix.z][tid]);
            float2 f = __half22float2(s_u[ix.w][tid]);
            float wsum = (w.x + w.y) + (w.z + w.w);
            float mx = (gshx + wsum) + w.x * a.x + w.y * c.x + w.z * d.x + w.w * f.x;
            float my = (gshy + wsum) + w.x * a.y + w.y * c.y + w.z * d.y + w.w * f.y;
            __stcs(O + (size_t)j * (HH / 2), make_float2(p[j].x * mx, p[j].y * my));
        }
    }
}

extern "C" void kernel_launch(void* const* d_in, const int* in_sizes, int n_in,
                              void* d_out, int out_size) {
    const float* x     = (const float*)d_in[0];  // input_embeds (B,S,H)
    const float* pb    = (const float*)d_in[1];  // prompt_base  (T,H)
    const float* pd    = (const float*)d_in[2];  // prompt_delta (T,H)
    const float* limes = (const float*)d_in[3];  // LiMEs        (E,H)
    const float* shv   = (const float*)d_in[4];  // LiME_shared  (H,)
    const float* gamma = (const float*)d_in[5];  // gamma        (1,)
    const float* W     = (const float*)d_in[6];  // W_proj       (H,H)
    float* out = (float*)d_out;                  // (B,T,H) f32

    k_reduce_s<<<dim3(HH / 256 + 1, BB), 256>>>(x, pb, pd);
    k_cond<<<dim3(EE, BB / 2), 256>>>(W);
    k_weights<<<dim3(TT / 4, BB), dim3(64, 4)>>>(pb, pd, gamma);
    k_out2<<<dim3(HH / CHUNK, TT / TTILE), 128>>>(pb, pd, limes, shv, gamma, out);
}